// round 2
// baseline (speedup 1.0000x reference)
#include <cuda_runtime.h>

#define ROWS 4096
#define COLS 8192
#define THREADS 256
#define NWARPS (THREADS / 32)
#define VPT (COLS / (THREADS * 4))   // 8 float4 per thread

__global__ void __launch_bounds__(THREADS)
sparsemax_kernel(const float* __restrict__ x, float* __restrict__ out) {
    const int row  = blockIdx.x;
    const int t    = threadIdx.x;
    const int warp = t >> 5;
    const int lane = t & 31;

    const float4* __restrict__ x4 = reinterpret_cast<const float4*>(x + (size_t)row * COLS);
    float4*       __restrict__ o4 = reinterpret_cast<float4*>(out + (size_t)row * COLS);

    // Front-batched coalesced loads: 8 x float4 per thread, stride THREADS.
    float4 v[VPT];
#pragma unroll
    for (int i = 0; i < VPT; i++) v[i] = x4[t + i * THREADS];

    __shared__ float s_sum[NWARPS];
    __shared__ float s_cnt[NWARPS];
    __shared__ float s_tau;

    // ---- init: tau0 = (sum(x) - 1) / N  (guarantees g(tau0) >= 0) ----
    float s = 0.f;
#pragma unroll
    for (int i = 0; i < VPT; i++) s += (v[i].x + v[i].y) + (v[i].z + v[i].w);
#pragma unroll
    for (int off = 16; off; off >>= 1) s += __shfl_xor_sync(0xffffffffu, s, off);
    if (lane == 0) s_sum[warp] = s;
    __syncthreads();
    if (t == 0) {
        float tot = 0.f;
#pragma unroll
        for (int w = 0; w < NWARPS; w++) tot += s_sum[w];
        s_tau = (tot - 1.0f) / (float)COLS;
    }
    __syncthreads();
    float tau = s_tau;

    // ---- Newton iterations on g(tau) = sum(relu(x - tau)) - 1 ----
    for (int iter = 0; iter < 32; iter++) {
        float ps = 0.f, pc = 0.f;
#pragma unroll
        for (int i = 0; i < VPT; i++) {
            if (v[i].x > tau) { ps += v[i].x; pc += 1.f; }
            if (v[i].y > tau) { ps += v[i].y; pc += 1.f; }
            if (v[i].z > tau) { ps += v[i].z; pc += 1.f; }
            if (v[i].w > tau) { ps += v[i].w; pc += 1.f; }
        }
#pragma unroll
        for (int off = 16; off; off >>= 1) {
            ps += __shfl_xor_sync(0xffffffffu, ps, off);
            pc += __shfl_xor_sync(0xffffffffu, pc, off);
        }
        if (lane == 0) { s_sum[warp] = ps; s_cnt[warp] = pc; }
        __syncthreads();
        if (t == 0) {
            float S = 0.f, C = 0.f;
#pragma unroll
            for (int w = 0; w < NWARPS; w++) { S += s_sum[w]; C += s_cnt[w]; }
            // C >= 1 whenever g(tau) > 0; guard anyway (keeps tau -> triggers convergence)
            s_tau = (C >= 0.5f) ? (S - 1.0f) / C : tau;
        }
        __syncthreads();
        float ntau = s_tau;
        if (ntau == tau) break;   // uniform: all threads read same smem value
        tau = ntau;
    }

    // ---- epilogue: out = max(x - tau, 0), coalesced float4 stores ----
#pragma unroll
    for (int i = 0; i < VPT; i++) {
        float4 r;
        r.x = fmaxf(v[i].x - tau, 0.f);
        r.y = fmaxf(v[i].y - tau, 0.f);
        r.z = fmaxf(v[i].z - tau, 0.f);
        r.w = fmaxf(v[i].w - tau, 0.f);
        o4[t + i * THREADS] = r;
    }
}

extern "C" void kernel_launch(void* const* d_in, const int* in_sizes, int n_in,
                              void* d_out, int out_size) {
    const float* x = (const float*)d_in[0];
    float* out = (float*)d_out;
    sparsemax_kernel<<<ROWS, THREADS>>>(x, out);
}